// round 12
// baseline (speedup 1.0000x reference)
#include <cuda_runtime.h>
#include <cuda_fp16.h>
#include <cstdint>

// ============================================================
// Typed relational GCN, sm_103 baseline PTX (no tcgen05 allowed).
//   out = sum_k (adj==k) @ (V@w_k) + bias,  N=8192, F=256, fp32.
//
// R12: stage2 in small decoupled CTAs: 128 threads = 4 warps of
// M32 x N64 (crossbar ratio 0.25), grid 256 -> 2 CTAs/SM, all
// resident in wave 1. Inter-CTA overlap hides barrier/dependency
// stalls. PRMT masks; 3-stage cp.async pipeline; R10 HMMA stage1.
// ============================================================

#define NROWS 8192
#define FEAT  256
#define NCHUNKS 128                           // K chunks of 64
#define STAGES 3
#define STAGE_BYTES (3 * 8 * 2 * 32 * 16)     // [type][nt][half][lane][16B] = 24576
#define SMEM_TOTAL (STAGES * STAGE_BYTES)     // 73728 (x2 CTAs/SM = 147456)

// B scratch, fragment-major fp16:
// [type(3)][ntile(32)][kchunk(128)][half(2)][lane(32)][16B] = 12.58 MB
__device__ __align__(256) uint8_t g_B[3u * 32u * 128u * 2u * 32u * 16u];

#define BS_HALF   512u
#define BS_CHUNK  1024u
#define BS_NTILE  131072u
#define BS_TYPE   4194304u

// stage1 smem: w fragments + 4 warp transpose buffers
#define S1_WFRAG_BYTES (16 * 8 * 32 * 8)      // 32768
#define S1_TBUF_BYTES  (32 * 66 * 2)          // 4224
#define S1_SMEM (S1_WFRAG_BYTES + 4 * S1_TBUF_BYTES)   // 49664

// ---------------- helpers ---------------------------------------------------

__device__ __forceinline__ uint32_t smem_u32(const void* p) {
    uint32_t a;
    asm("{ .reg .u64 t; cvta.to.shared.u64 t, %1; cvt.u32.u64 %0, t; }" : "=r"(a) : "l"(p));
    return a;
}

__device__ __forceinline__ uint32_t prmt(uint32_t a, uint32_t b, uint32_t sel) {
    uint32_t r;
    asm("prmt.b32 %0, %1, %2, %3;" : "=r"(r) : "r"(a), "r"(b), "r"(sel));
    return r;
}

__device__ __forceinline__ uint32_t pack4(int a, int b, int c, int d) {
    uint32_t x, y, r;
    asm("prmt.b32 %0, %1, %2, 0x40;"   : "=r"(x) : "r"(a), "r"(b));
    asm("prmt.b32 %0, %1, %2, 0x40;"   : "=r"(y) : "r"(c), "r"(d));
    asm("prmt.b32 %0, %1, %2, 0x5410;" : "=r"(r) : "r"(x), "r"(y));
    return r;
}

__device__ __forceinline__ uint32_t f2h2(float a, float b) {
    __half2 h = __floats2half2_rn(a, b);
    return *reinterpret_cast<uint32_t*>(&h);
}

__device__ __forceinline__ void mma_f16(float* c,
                                        uint32_t a0, uint32_t a1, uint32_t a2, uint32_t a3,
                                        uint32_t b0, uint32_t b1) {
    asm volatile(
        "mma.sync.aligned.m16n8k16.row.col.f32.f16.f16.f32 "
        "{%0,%1,%2,%3}, {%4,%5,%6,%7}, {%8,%9}, {%0,%1,%2,%3};"
        : "+f"(c[0]), "+f"(c[1]), "+f"(c[2]), "+f"(c[3])
        : "r"(a0), "r"(a1), "r"(a2), "r"(a3), "r"(b0), "r"(b1));
}

__device__ __forceinline__ void cp_async16(uint32_t smem_addr, const void* gptr) {
    asm volatile("cp.async.cg.shared.global [%0], [%1], 16;"
                 :: "r"(smem_addr), "l"(gptr) : "memory");
}
#define CP_COMMIT() asm volatile("cp.async.commit_group;" ::: "memory")
#define CP_WAIT1()  asm volatile("cp.async.wait_group 1;" ::: "memory")
#define CP_WAIT0()  asm volatile("cp.async.wait_group 0;" ::: "memory")

__device__ __forceinline__ uint4 lds128(uint32_t addr) {
    uint4 v;
    asm volatile("ld.shared.v4.u32 {%0,%1,%2,%3}, [%4];"
                 : "=r"(v.x), "=r"(v.y), "=r"(v.z), "=r"(v.w) : "r"(addr));
    return v;
}

// ---------------- Stage 1: H_k = V @ w_k on HMMA (unchanged R10) -----------
// grid (64 j-tiles of 128, 4 n-quarters, 3 types), block 128 (4 warps).

__global__ void __launch_bounds__(128)
stage1_kernel(const float* __restrict__ V,
              const float* __restrict__ w1,
              const float* __restrict__ w2,
              const float* __restrict__ w3) {
    extern __shared__ uint8_t s1mem[];
    const int j0 = blockIdx.x * 128;
    const int n0 = blockIdx.y * 64;
    const int type = blockIdx.z;
    const float* w = (type == 0) ? w1 : (type == 1) ? w2 : w3;

    const int tid = threadIdx.x;
    const int wid = tid >> 5, l = tid & 31;
    const int li = l & 3, lr = l >> 2;

    uint2* wfrag = (uint2*)s1mem;
#pragma unroll
    for (int q = 0; q < 32; q++) {
        int idx = tid + 128 * q;
        int ks = idx >> 8;
        int nt = (idx >> 5) & 7;
        int l2 = idx & 31;
        int n = n0 + 8 * nt + (l2 >> 2);
        int k0 = 16 * ks + 2 * (l2 & 3);
        float f0 = __ldg(&w[(size_t)k0 * 256 + n]);
        float f1 = __ldg(&w[(size_t)(k0 + 1) * 256 + n]);
        float f2 = __ldg(&w[(size_t)(k0 + 8) * 256 + n]);
        float f3 = __ldg(&w[(size_t)(k0 + 9) * 256 + n]);
        wfrag[idx] = make_uint2(f2h2(f0, f1), f2h2(f2, f3));
    }
    __syncthreads();

    const int rw = j0 + 32 * wid;
    float acc[2][8][4];
#pragma unroll
    for (int m = 0; m < 2; m++)
#pragma unroll
        for (int nt = 0; nt < 8; nt++)
#pragma unroll
            for (int r = 0; r < 4; r++) acc[m][nt][r] = 0.f;

#pragma unroll
    for (int ks = 0; ks < 16; ks++) {
        const int k0 = 16 * ks + 2 * li;
        uint32_t a[2][4];
#pragma unroll
        for (int m = 0; m < 2; m++) {
            const float* p0 = V + (size_t)(rw + 16 * m + lr) * 256;
            const float* p1 = p0 + 8 * 256;
            float2 x0 = *(const float2*)(p0 + k0);
            float2 x1 = *(const float2*)(p1 + k0);
            float2 x2 = *(const float2*)(p0 + k0 + 8);
            float2 x3 = *(const float2*)(p1 + k0 + 8);
            a[m][0] = f2h2(x0.x, x0.y);
            a[m][1] = f2h2(x1.x, x1.y);
            a[m][2] = f2h2(x2.x, x2.y);
            a[m][3] = f2h2(x3.x, x3.y);
        }
#pragma unroll
        for (int nt = 0; nt < 8; nt++) {
            uint2 bw = wfrag[(ks * 8 + nt) * 32 + l];
            mma_f16(acc[0][nt], a[0][0], a[0][1], a[0][2], a[0][3], bw.x, bw.y);
            mma_f16(acc[1][nt], a[1][0], a[1][1], a[1][2], a[1][3], bw.x, bw.y);
        }
    }

    __half* tb = (__half*)(s1mem + S1_WFRAG_BYTES + wid * S1_TBUF_BYTES);
#pragma unroll
    for (int m = 0; m < 2; m++) {
#pragma unroll
        for (int nt = 0; nt < 8; nt++) {
            const int jrow = 16 * m + lr;
            const int nloc = 8 * nt + 2 * li;
            __half2 lo = __floats2half2_rn(acc[m][nt][0], acc[m][nt][1]);
            __half2 hi = __floats2half2_rn(acc[m][nt][2], acc[m][nt][3]);
            *(__half2*)&tb[jrow * 66 + nloc] = lo;
            *(__half2*)&tb[(jrow + 8) * 66 + nloc] = hi;
        }
    }
    __syncwarp();

    const int kc = (j0 + 32 * wid) >> 6;
    const int hl = wid & 1;
#pragma unroll
    for (int nt = 0; nt < 8; nt++) {
        const int nloc = 8 * nt + lr;
        const int jb = 2 * li;
        ushort h[8];
#pragma unroll
        for (int i = 0; i < 2; i++) {
            h[4 * i + 0] = *(ushort*)&tb[(jb + 16 * i + 0) * 66 + nloc];
            h[4 * i + 1] = *(ushort*)&tb[(jb + 16 * i + 1) * 66 + nloc];
            h[4 * i + 2] = *(ushort*)&tb[(jb + 16 * i + 8) * 66 + nloc];
            h[4 * i + 3] = *(ushort*)&tb[(jb + 16 * i + 9) * 66 + nloc];
        }
        uint4 val;
        val.x = (uint32_t)h[0] | ((uint32_t)h[1] << 16);
        val.y = (uint32_t)h[2] | ((uint32_t)h[3] << 16);
        val.z = (uint32_t)h[4] | ((uint32_t)h[5] << 16);
        val.w = (uint32_t)h[6] | ((uint32_t)h[7] << 16);
        size_t off = (size_t)type * BS_TYPE
                   + (size_t)(blockIdx.y * 8 + nt) * BS_NTILE
                   + (size_t)kc * BS_CHUNK + (size_t)hl * BS_HALF + (size_t)l * 16;
        *(uint4*)&g_B[off] = val;
    }
}

// ---------------- Stage 2: mask-GEMM, 4 warps of M32 x N64 ------------------
// grid 256: bid -> (m_tile = bid>>2 of 128 rows, n_q = bid&3 of 64 feats).
// 128 threads; warp wid owns rows [i0 + wid*32, +32), all 64 CTA feats.

__global__ void __launch_bounds__(128)
stage2_kernel(const int* __restrict__ adj,
              const float* __restrict__ bias,
              float* __restrict__ out) {
    extern __shared__ uint8_t smem[];
    const uint32_t smem_base = smem_u32(smem);

    const int tid = threadIdx.x;
    const int wid = tid >> 5, l = tid & 31;
    const int m_tile = blockIdx.x >> 2;
    const int n_q = blockIdx.x & 3;
    const int i0 = m_tile * 128;
    const int li = l & 3;

    const int r0 = i0 + wid * 32 + (l >> 2);
    const int2* ap[2][2];
#pragma unroll
    for (int m = 0; m < 2; m++)
#pragma unroll
        for (int ab = 0; ab < 2; ab++)
            ap[m][ab] = (const int2*)(adj + (size_t)(r0 + 16 * m + 8 * ab) * NROWS);

    float acc[2][8][4];
#pragma unroll
    for (int m = 0; m < 2; m++)
#pragma unroll
        for (int nt = 0; nt < 8; nt++)
#pragma unroll
            for (int r = 0; r < 4; r++) acc[m][nt][r] = 0.f;

    // prologue: stage chunks 0 and 1 (1536 x 16B per chunk, 12 per thread)
#pragma unroll
    for (int p = 0; p < 2; p++) {
#pragma unroll
        for (int q = 0; q < 12; q++) {
            int idx = tid + 128 * q;                 // 0..1535
            int type = idx >> 9;
            int rem = idx & 511;
            int nt = rem >> 6;
            int hl = (rem >> 5) & 1;
            int lane = rem & 31;
            const uint8_t* src = g_B + (size_t)type * BS_TYPE
                + (size_t)(n_q * 8 + nt) * BS_NTILE + (size_t)p * BS_CHUNK
                + (size_t)hl * BS_HALF + (size_t)lane * 16;
            cp_async16(smem_base + p * STAGE_BYTES + idx * 16, src);
        }
        CP_COMMIT();
    }

    // adj for chunk 0: load + pack
    uint32_t pk[2][2][4];
#pragma unroll
    for (int m = 0; m < 2; m++)
#pragma unroll
        for (int ab = 0; ab < 2; ab++)
#pragma unroll
            for (int s = 0; s < 4; s++) {
                int2 a0 = ap[m][ab][8 * s + li];
                int2 a1 = ap[m][ab][8 * s + li + 4];
                pk[m][ab][s] = pack4(a0.x, a0.y, a1.x, a1.y);
            }

    for (int c = 0; c < NCHUNKS; c++) {
        // chunk c ready when at most 1 group (c+1) still in flight
        CP_WAIT1();
        __syncthreads();   // c visible; all warps done with buffer (c-1)%3

        // stage chunk c+2 into buffer (c+2)%3 (freed by the sync above)
        if (c + 2 < NCHUNKS) {
            const int p = c + 2;
            const int pb = p % 3;
#pragma unroll
            for (int q = 0; q < 12; q++) {
                int idx = tid + 128 * q;
                int type = idx >> 9;
                int rem = idx & 511;
                int nt = rem >> 6;
                int hl = (rem >> 5) & 1;
                int lane = rem & 31;
                const uint8_t* src = g_B + (size_t)type * BS_TYPE
                    + (size_t)(n_q * 8 + nt) * BS_NTILE + (size_t)p * BS_CHUNK
                    + (size_t)hl * BS_HALF + (size_t)lane * 16;
                cp_async16(smem_base + pb * STAGE_BYTES + idx * 16, src);
            }
        }
        CP_COMMIT();

        // issue adj loads for chunk c+1 (land during this chunk's MMAs)
        int2 nv[2][2][4][2];
        if (c + 1 < NCHUNKS) {
            const int base = (c + 1) * 32;
#pragma unroll
            for (int m = 0; m < 2; m++)
#pragma unroll
                for (int ab = 0; ab < 2; ab++)
#pragma unroll
                    for (int s = 0; s < 4; s++) {
                        nv[m][ab][s][0] = ap[m][ab][base + 8 * s + li];
                        nv[m][ab][s][1] = ap[m][ab][base + 8 * s + li + 4];
                    }
        }

        const uint32_t sb = smem_base + (c % 3) * STAGE_BYTES;
#pragma unroll
        for (int t = 0; t < 3; t++) {
            const uint32_t cmp = 0x01010101u * (t + 1);
            uint32_t am[2][4][4];
#pragma unroll
            for (int m = 0; m < 2; m++)
#pragma unroll
                for (int s = 0; s < 4; s++) {
                    uint32_t eA = __vcmpeq4(pk[m][0][s], cmp) & 0x3C3C3C3Cu;
                    uint32_t eB = __vcmpeq4(pk[m][1][s], cmp) & 0x3C3C3C3Cu;
                    am[m][s][0] = prmt(eA, 0u, 0x1404u);
                    am[m][s][1] = prmt(eB, 0u, 0x1404u);
                    am[m][s][2] = prmt(eA, 0u, 0x3424u);
                    am[m][s][3] = prmt(eB, 0u, 0x3424u);
                }
            // nt halves of 4: cache B frags in regs, s-outer / nt-inner issue
#pragma unroll
            for (int h = 0; h < 2; h++) {
                uint4 ub[4][2];
#pragma unroll
                for (int n4 = 0; n4 < 4; n4++) {
                    const int ntg = h * 4 + n4;
                    const uint32_t base = sb + (uint32_t)(((t * 8 + ntg) * 2) * 512 + l * 16);
                    ub[n4][0] = lds128(base);
                    ub[n4][1] = lds128(base + 512);
                }
#pragma unroll
                for (int s = 0; s < 4; s++) {
#pragma unroll
                    for (int n4 = 0; n4 < 4; n4++) {
                        const uint32_t b0 = (s & 1) ? ub[n4][s >> 1].z : ub[n4][s >> 1].x;
                        const uint32_t b1 = (s & 1) ? ub[n4][s >> 1].w : ub[n4][s >> 1].y;
#pragma unroll
                        for (int m = 0; m < 2; m++)
                            mma_f16(acc[m][h * 4 + n4],
                                    am[m][s][0], am[m][s][1], am[m][s][2], am[m][s][3],
                                    b0, b1);
                    }
                }
            }
        }

        // pack next chunk's adj
        if (c + 1 < NCHUNKS) {
#pragma unroll
            for (int m = 0; m < 2; m++)
#pragma unroll
                for (int ab = 0; ab < 2; ab++)
#pragma unroll
                    for (int s = 0; s < 4; s++)
                        pk[m][ab][s] = pack4(nv[m][ab][s][0].x, nv[m][ab][s][0].y,
                                             nv[m][ab][s][1].x, nv[m][ab][s][1].y);
        }
    }

    CP_WAIT0();

    // epilogue: out = acc + bias
#pragma unroll
    for (int m = 0; m < 2; m++) {
        const int rowA = r0 + 16 * m;
#pragma unroll
        for (int nt = 0; nt < 8; nt++) {
            int col = n_q * 64 + nt * 8 + 2 * li;
            float b0 = __ldg(&bias[col]);
            float b1 = __ldg(&bias[col + 1]);
            float2 w0 = make_float2(acc[m][nt][0] + b0, acc[m][nt][1] + b1);
            float2 w1 = make_float2(acc[m][nt][2] + b0, acc[m][nt][3] + b1);
            *(float2*)&out[(size_t)rowA * FEAT + col] = w0;
            *(float2*)&out[(size_t)(rowA + 8) * FEAT + col] = w1;
        }
    }
}

// ---------------- launch ---------------------------------------------------

extern "C" void kernel_launch(void* const* d_in, const int* in_sizes, int n_in,
                              void* d_out, int out_size) {
    const float* V    = (const float*)d_in[0];
    const int*   adj  = (const int*)d_in[1];
    const float* w1   = (const float*)d_in[2];
    const float* w2   = (const float*)d_in[3];
    const float* w3   = (const float*)d_in[4];
    const float* bias = (const float*)d_in[5];
    float* out = (float*)d_out;

    cudaFuncSetAttribute(stage1_kernel,
                         cudaFuncAttributeMaxDynamicSharedMemorySize, S1_SMEM);
    cudaFuncSetAttribute(stage2_kernel,
                         cudaFuncAttributeMaxDynamicSharedMemorySize, SMEM_TOTAL);

    stage1_kernel<<<dim3(64, 4, 3), 128, S1_SMEM>>>(V, w1, w2, w3);
    stage2_kernel<<<256, 128, SMEM_TOTAL>>>(adj, bias, out);
}

// round 14
// speedup vs baseline: 1.7671x; 1.7671x over previous
#include <cuda_runtime.h>
#include <cuda_fp16.h>
#include <cstdint>

// ============================================================
// Typed relational GCN, sm_103 baseline PTX (no tcgen05 allowed).
//   out = sum_k (adj==k) @ (V@w_k) + bias,  N=8192, F=256, fp32.
//
// R13: stage2 load-balanced across ALL 148 SMs. Global work list =
// 128 (M128 x N128) tiles x 128 kchunks = 16384 units, split into
// 148 contiguous runs (~110.7 chunks each). Each CTA runs 1-2
// (tile, chunk-range) segments with the UNCHANGED R10 inner loop,
// stores fp32 partials; fixup kernel sums 2-3 partials/tile + bias.
// Deterministic (fixed assignment). Stage1 = R10 HMMA version.
// ============================================================

#define NROWS 8192
#define FEAT  256
#define NCHUNKS 128
#define TOTUNITS 16384                        // 128 tiles * 128 chunks
#define NCTA2 148
#define STAGES 4
#define STAGE_BYTES (3 * 16 * 2 * 32 * 16)    // 49152
#define SMEM_TOTAL (STAGES * STAGE_BYTES)     // 196608

// B scratch, fragment-major fp16:
// [type(3)][ntile(32)][kchunk(128)][half(2)][lane(32)][16B] = 12.58 MB
__device__ __align__(256) uint8_t g_B[3u * 32u * 128u * 2u * 32u * 16u];

// per-(CTA, segment) fp32 partial tiles: 148 * 2 * 128*128 * 4B = 19.4 MB
__device__ __align__(256) float g_part[NCTA2][2][128 * 128];

#define BS_HALF   512u
#define BS_CHUNK  1024u
#define BS_NTILE  131072u
#define BS_TYPE   4194304u

#define S1_WFRAG_BYTES (16 * 8 * 32 * 8)      // 32768
#define S1_TBUF_BYTES  (32 * 66 * 2)          // 4224
#define S1_SMEM (S1_WFRAG_BYTES + 4 * S1_TBUF_BYTES)

// ---------------- helpers ---------------------------------------------------

__device__ __forceinline__ uint32_t smem_u32(const void* p) {
    uint32_t a;
    asm("{ .reg .u64 t; cvta.to.shared.u64 t, %1; cvt.u32.u64 %0, t; }" : "=r"(a) : "l"(p));
    return a;
}

__device__ __forceinline__ uint32_t prmt(uint32_t a, uint32_t b, uint32_t sel) {
    uint32_t r;
    asm("prmt.b32 %0, %1, %2, %3;" : "=r"(r) : "r"(a), "r"(b), "r"(sel));
    return r;
}

__device__ __forceinline__ uint32_t pack4(int a, int b, int c, int d) {
    uint32_t x, y, r;
    asm("prmt.b32 %0, %1, %2, 0x40;"   : "=r"(x) : "r"(a), "r"(b));
    asm("prmt.b32 %0, %1, %2, 0x40;"   : "=r"(y) : "r"(c), "r"(d));
    asm("prmt.b32 %0, %1, %2, 0x5410;" : "=r"(r) : "r"(x), "r"(y));
    return r;
}

__device__ __forceinline__ uint32_t f2h2(float a, float b) {
    __half2 h = __floats2half2_rn(a, b);
    return *reinterpret_cast<uint32_t*>(&h);
}

__device__ __forceinline__ void mma_f16(float* c,
                                        uint32_t a0, uint32_t a1, uint32_t a2, uint32_t a3,
                                        uint32_t b0, uint32_t b1) {
    asm volatile(
        "mma.sync.aligned.m16n8k16.row.col.f32.f16.f16.f32 "
        "{%0,%1,%2,%3}, {%4,%5,%6,%7}, {%8,%9}, {%0,%1,%2,%3};"
        : "+f"(c[0]), "+f"(c[1]), "+f"(c[2]), "+f"(c[3])
        : "r"(a0), "r"(a1), "r"(a2), "r"(a3), "r"(b0), "r"(b1));
}

__device__ __forceinline__ void cp_async16(uint32_t smem_addr, const void* gptr) {
    asm volatile("cp.async.cg.shared.global [%0], [%1], 16;"
                 :: "r"(smem_addr), "l"(gptr) : "memory");
}
#define CP_COMMIT() asm volatile("cp.async.commit_group;" ::: "memory")
#define CP_WAIT3()  asm volatile("cp.async.wait_group 3;" ::: "memory")
#define CP_WAIT0()  asm volatile("cp.async.wait_group 0;" ::: "memory")

// ---------------- Stage 1: H_k = V @ w_k on HMMA (unchanged R10) -----------

__global__ void __launch_bounds__(128)
stage1_kernel(const float* __restrict__ V,
              const float* __restrict__ w1,
              const float* __restrict__ w2,
              const float* __restrict__ w3) {
    extern __shared__ uint8_t s1mem[];
    const int j0 = blockIdx.x * 128;
    const int n0 = blockIdx.y * 64;
    const int type = blockIdx.z;
    const float* w = (type == 0) ? w1 : (type == 1) ? w2 : w3;

    const int tid = threadIdx.x;
    const int wid = tid >> 5, l = tid & 31;
    const int li = l & 3, lr = l >> 2;

    uint2* wfrag = (uint2*)s1mem;
#pragma unroll
    for (int q = 0; q < 32; q++) {
        int idx = tid + 128 * q;
        int ks = idx >> 8;
        int nt = (idx >> 5) & 7;
        int l2 = idx & 31;
        int n = n0 + 8 * nt + (l2 >> 2);
        int k0 = 16 * ks + 2 * (l2 & 3);
        float f0 = __ldg(&w[(size_t)k0 * 256 + n]);
        float f1 = __ldg(&w[(size_t)(k0 + 1) * 256 + n]);
        float f2 = __ldg(&w[(size_t)(k0 + 8) * 256 + n]);
        float f3 = __ldg(&w[(size_t)(k0 + 9) * 256 + n]);
        wfrag[idx] = make_uint2(f2h2(f0, f1), f2h2(f2, f3));
    }
    __syncthreads();

    const int rw = j0 + 32 * wid;
    float acc[2][8][4];
#pragma unroll
    for (int m = 0; m < 2; m++)
#pragma unroll
        for (int nt = 0; nt < 8; nt++)
#pragma unroll
            for (int r = 0; r < 4; r++) acc[m][nt][r] = 0.f;

#pragma unroll
    for (int ks = 0; ks < 16; ks++) {
        const int k0 = 16 * ks + 2 * li;
        uint32_t a[2][4];
#pragma unroll
        for (int m = 0; m < 2; m++) {
            const float* p0 = V + (size_t)(rw + 16 * m + lr) * 256;
            const float* p1 = p0 + 8 * 256;
            float2 x0 = *(const float2*)(p0 + k0);
            float2 x1 = *(const float2*)(p1 + k0);
            float2 x2 = *(const float2*)(p0 + k0 + 8);
            float2 x3 = *(const float2*)(p1 + k0 + 8);
            a[m][0] = f2h2(x0.x, x0.y);
            a[m][1] = f2h2(x1.x, x1.y);
            a[m][2] = f2h2(x2.x, x2.y);
            a[m][3] = f2h2(x3.x, x3.y);
        }
#pragma unroll
        for (int nt = 0; nt < 8; nt++) {
            uint2 bw = wfrag[(ks * 8 + nt) * 32 + l];
            mma_f16(acc[0][nt], a[0][0], a[0][1], a[0][2], a[0][3], bw.x, bw.y);
            mma_f16(acc[1][nt], a[1][0], a[1][1], a[1][2], a[1][3], bw.x, bw.y);
        }
    }

    __half* tb = (__half*)(s1mem + S1_WFRAG_BYTES + wid * S1_TBUF_BYTES);
#pragma unroll
    for (int m = 0; m < 2; m++) {
#pragma unroll
        for (int nt = 0; nt < 8; nt++) {
            const int jrow = 16 * m + lr;
            const int nloc = 8 * nt + 2 * li;
            __half2 lo = __floats2half2_rn(acc[m][nt][0], acc[m][nt][1]);
            __half2 hi = __floats2half2_rn(acc[m][nt][2], acc[m][nt][3]);
            *(__half2*)&tb[jrow * 66 + nloc] = lo;
            *(__half2*)&tb[(jrow + 8) * 66 + nloc] = hi;
        }
    }
    __syncwarp();

    const int kc = (j0 + 32 * wid) >> 6;
    const int hl = wid & 1;
#pragma unroll
    for (int nt = 0; nt < 8; nt++) {
        const int nloc = 8 * nt + lr;
        const int jb = 2 * li;
        ushort h[8];
#pragma unroll
        for (int i = 0; i < 2; i++) {
            h[4 * i + 0] = *(ushort*)&tb[(jb + 16 * i + 0) * 66 + nloc];
            h[4 * i + 1] = *(ushort*)&tb[(jb + 16 * i + 1) * 66 + nloc];
            h[4 * i + 2] = *(ushort*)&tb[(jb + 16 * i + 8) * 66 + nloc];
            h[4 * i + 3] = *(ushort*)&tb[(jb + 16 * i + 9) * 66 + nloc];
        }
        uint4 val;
        val.x = (uint32_t)h[0] | ((uint32_t)h[1] << 16);
        val.y = (uint32_t)h[2] | ((uint32_t)h[3] << 16);
        val.z = (uint32_t)h[4] | ((uint32_t)h[5] << 16);
        val.w = (uint32_t)h[6] | ((uint32_t)h[7] << 16);
        size_t off = (size_t)type * BS_TYPE
                   + (size_t)(blockIdx.y * 8 + nt) * BS_NTILE
                   + (size_t)kc * BS_CHUNK + (size_t)hl * BS_HALF + (size_t)l * 16;
        *(uint4*)&g_B[off] = val;
    }
}

// ---------------- Stage 2: mask-GEMM, balanced segments ---------------------
// grid 148, 256 threads. CTA i owns global chunk units [16384i/148, 16384(i+1)/148),
// i.e. 1-2 (tile, chunk-range) segments. R10 inner loop unchanged.
// Partials to g_part[i][seg]; no bias here.

__global__ void __launch_bounds__(256, 1)
stage2_kernel(const int* __restrict__ adj) {
    extern __shared__ uint8_t smem[];
    const uint32_t smem_base = smem_u32(smem);

    const int tid = threadIdx.x;
    const int wid = tid >> 5, l = tid & 31;
    const int li = l & 3;

    const uint32_t ci = blockIdx.x;
    const uint32_t start = (uint32_t)(((uint64_t)TOTUNITS * ci) / NCTA2);
    const uint32_t end   = (uint32_t)(((uint64_t)TOTUNITS * (ci + 1)) / NCTA2);
    const int t0 = (int)(start >> 7), t1 = (int)((end - 1) >> 7);
    const int nseg = (t1 > t0) ? 2 : 1;

    for (int sgi = 0; sgi < nseg; sgi++) {
        const int tile = (sgi == 0) ? t0 : t1;
        const int clo = (sgi == 0) ? (int)(start & 127u) : 0;
        const int chi = (sgi == 0) ? ((t1 > t0) ? 128 : (int)(end - ((uint32_t)t0 << 7)))
                                   : (int)(end - ((uint32_t)t1 << 7));
        const int m_tile = tile >> 1;
        const int n_half = tile & 1;
        const int i0 = m_tile * 128;

        const int rowA = i0 + wid * 16 + (l >> 2);
        const int2* aA = (const int2*)(adj + (size_t)rowA * NROWS);
        const int2* aB = (const int2*)(adj + (size_t)(rowA + 8) * NROWS);

        float acc[16][4];
#pragma unroll
        for (int nt = 0; nt < 16; nt++)
#pragma unroll
            for (int r = 0; r < 4; r++) acc[nt][r] = 0.f;

        // prologue: exactly 3 commits (empty beyond chi)
        for (int p = clo; p < clo + 3; p++) {
            if (p < chi) {
#pragma unroll
                for (int q = 0; q < 12; q++) {
                    int idx = tid + 256 * q;
                    int type = idx >> 10;
                    int rem = idx & 1023;
                    int nt = rem >> 6;
                    int hl = (rem >> 5) & 1;
                    int lane = rem & 31;
                    const uint8_t* src = g_B + (size_t)type * BS_TYPE
                        + (size_t)(n_half * 16 + nt) * BS_NTILE + (size_t)p * BS_CHUNK
                        + (size_t)hl * BS_HALF + (size_t)lane * 16;
                    cp_async16(smem_base + (p & 3) * STAGE_BYTES + idx * 16, src);
                }
            }
            CP_COMMIT();
        }

        // preload adj chunk clo
        int2 vA0[4], vA1[4], vB0[4], vB1[4];
        {
            const int base = clo * 32;
#pragma unroll
            for (int s = 0; s < 4; s++) {
                vA0[s] = aA[base + 8 * s + li];
                vA1[s] = aA[base + 8 * s + li + 4];
                vB0[s] = aB[base + 8 * s + li];
                vB1[s] = aB[base + 8 * s + li + 4];
            }
        }

        for (int c = clo; c < chi; c++) {
            __syncthreads();   // all warps done with buffer being overwritten
            if (c + 3 < chi) {
                const int p = c + 3;
#pragma unroll
                for (int q = 0; q < 12; q++) {
                    int idx = tid + 256 * q;
                    int type = idx >> 10;
                    int rem = idx & 1023;
                    int nt = rem >> 6;
                    int hl = (rem >> 5) & 1;
                    int lane = rem & 31;
                    const uint8_t* src = g_B + (size_t)type * BS_TYPE
                        + (size_t)(n_half * 16 + nt) * BS_NTILE + (size_t)p * BS_CHUNK
                        + (size_t)hl * BS_HALF + (size_t)lane * 16;
                    cp_async16(smem_base + (p & 3) * STAGE_BYTES + idx * 16, src);
                }
            }
            CP_COMMIT();

            uint32_t pkA[4], pkB[4];
#pragma unroll
            for (int s = 0; s < 4; s++) {
                pkA[s] = pack4(vA0[s].x, vA0[s].y, vA1[s].x, vA1[s].y);
                pkB[s] = pack4(vB0[s].x, vB0[s].y, vB1[s].x, vB1[s].y);
            }

            if (c + 1 < chi) {
                const int base = (c + 1) * 32;
#pragma unroll
                for (int s = 0; s < 4; s++) {
                    vA0[s] = aA[base + 8 * s + li];
                    vA1[s] = aA[base + 8 * s + li + 4];
                    vB0[s] = aB[base + 8 * s + li];
                    vB1[s] = aB[base + 8 * s + li + 4];
                }
            }

            CP_WAIT3();
            __syncthreads();

            const uint32_t sb = smem_base + (c & 3) * STAGE_BYTES;
#pragma unroll
            for (int t = 0; t < 3; t++) {
                const uint32_t cmp = 0x01010101u * (t + 1);
                uint32_t am[4][4];
#pragma unroll
                for (int s = 0; s < 4; s++) {
                    uint32_t eA = __vcmpeq4(pkA[s], cmp) & 0x3C3C3C3Cu;
                    uint32_t eB = __vcmpeq4(pkB[s], cmp) & 0x3C3C3C3Cu;
                    am[s][0] = prmt(eA, 0u, 0x1404u);
                    am[s][1] = prmt(eB, 0u, 0x1404u);
                    am[s][2] = prmt(eA, 0u, 0x3424u);
                    am[s][3] = prmt(eB, 0u, 0x3424u);
                }
#pragma unroll
                for (int nt = 0; nt < 16; nt++) {
                    const uint32_t base = sb + (uint32_t)(((t * 16 + nt) * 2) * 512 + l * 16);
                    uint4 u0, u1;
                    asm volatile("ld.shared.v4.u32 {%0,%1,%2,%3}, [%4];"
                                 : "=r"(u0.x), "=r"(u0.y), "=r"(u0.z), "=r"(u0.w) : "r"(base));
                    asm volatile("ld.shared.v4.u32 {%0,%1,%2,%3}, [%4];"
                                 : "=r"(u1.x), "=r"(u1.y), "=r"(u1.z), "=r"(u1.w) : "r"(base + 512));
                    mma_f16(acc[nt], am[0][0], am[0][1], am[0][2], am[0][3], u0.x, u0.y);
                    mma_f16(acc[nt], am[1][0], am[1][1], am[1][2], am[1][3], u0.z, u0.w);
                    mma_f16(acc[nt], am[2][0], am[2][1], am[2][2], am[2][3], u1.x, u1.y);
                    mma_f16(acc[nt], am[3][0], am[3][1], am[3][2], am[3][3], u1.z, u1.w);
                }
            }
        }

        // segment epilogue: partials (no bias)
        float* part = g_part[ci][sgi];
        const int rloc = wid * 16 + (l >> 2);
#pragma unroll
        for (int nt = 0; nt < 16; nt++) {
            int col = nt * 8 + 2 * li;
            *(float2*)&part[rloc * 128 + col] = make_float2(acc[nt][0], acc[nt][1]);
            *(float2*)&part[(rloc + 8) * 128 + col] = make_float2(acc[nt][2], acc[nt][3]);
        }
        __syncthreads();   // protect smem before next segment's prologue
    }
}

// ---------------- Fixup: sum partials per tile + bias -----------------------
// grid 128 (one CTA per tile), 256 threads.

__global__ void __launch_bounds__(256)
fixup_kernel(const float* __restrict__ bias, float* __restrict__ out) {
    const int t = blockIdx.x;
    const int m_tile = t >> 1, n_half = t & 1;
    const int i0 = m_tile * 128;
    const int n0 = n_half * 128;

    // find covering (cta, seg) sources (2-3 of them)
    int src_i[3], src_s[3];
    int ns = 0;
    int ic = (t * NCTA2) >> 7;
    int lo = ic - 1 < 0 ? 0 : ic - 1;
    int hi = ic + 2 > NCTA2 - 1 ? NCTA2 - 1 : ic + 2;
    for (int i = lo; i <= hi; i++) {
        uint32_t s0 = (uint32_t)(((uint64_t)TOTUNITS * i) / NCTA2);
        uint32_t e0 = (uint32_t)(((uint64_t)TOTUNITS * (i + 1)) / NCTA2);
        int tt0 = (int)(s0 >> 7), tt1 = (int)((e0 - 1) >> 7);
        if (tt0 == t)                      { src_i[ns] = i; src_s[ns] = 0; ns++; }
        else if (tt1 == t && tt1 != tt0)   { src_i[ns] = i; src_s[ns] = 1; ns++; }
    }

    for (int e = threadIdx.x; e < 4096; e += 256) {
        const int r = e >> 5;
        const int c4 = (e & 31) * 4;
        float4 s = make_float4(0.f, 0.f, 0.f, 0.f);
        for (int k = 0; k < ns; k++) {
            float4 v = *(const float4*)&g_part[src_i[k]][src_s[k]][r * 128 + c4];
            s.x += v.x; s.y += v.y; s.z += v.z; s.w += v.w;
        }
        float4 b = *(const float4*)&bias[n0 + c4];
        s.x += b.x; s.y += b.y; s.z += b.z; s.w += b.w;
        *(float4*)&out[(size_t)(i0 + r) * FEAT + n0 + c4] = s;
    }
}

// ---------------- launch ---------------------------------------------------

extern "C" void kernel_launch(void* const* d_in, const int* in_sizes, int n_in,
                              void* d_out, int out_size) {
    const float* V    = (const float*)d_in[0];
    const int*   adj  = (const int*)d_in[1];
    const float* w1   = (const float*)d_in[2];
    const float* w2   = (const float*)d_in[3];
    const float* w3   = (const float*)d_in[4];
    const float* bias = (const float*)d_in[5];
    float* out = (float*)d_out;

    cudaFuncSetAttribute(stage1_kernel,
                         cudaFuncAttributeMaxDynamicSharedMemorySize, S1_SMEM);
    cudaFuncSetAttribute(stage2_kernel,
                         cudaFuncAttributeMaxDynamicSharedMemorySize, SMEM_TOTAL);

    stage1_kernel<<<dim3(64, 4, 3), 128, S1_SMEM>>>(V, w1, w2, w3);
    stage2_kernel<<<NCTA2, 256, SMEM_TOTAL>>>(adj);
    fixup_kernel<<<128, 256>>>(bias, out);
}

// round 16
// speedup vs baseline: 1.8934x; 1.0715x over previous
#include <cuda_runtime.h>
#include <cuda_fp16.h>
#include <cstdint>

// ============================================================
// Typed relational GCN, sm_103 baseline PTX (no tcgen05 allowed).
//   out = sum_k (adj==k) @ (V@w_k) + bias,  N=8192, F=256, fp32.
//
// R14: stage2 K-chunk doubled to 128 with 2-deep pipeline and ONE
// barrier per chunk (sync points 256 -> 55 per CTA). Balanced
// 148-CTA partition (R13-validated) in units of 64 bigchunks/tile.
// Stage1: transpose buffers aliased over wfrag (smem 49.7->32.8 KB,
// occupancy cap lifted). Fixup unchanged.
// ============================================================

#define NROWS 8192
#define FEAT  256
#define NBIG  64                              // K bigchunks of 128
#define TOTUNITS 8192                         // 128 tiles * 64 bigchunks
#define NCTA2 148
#define HALF_BYTES 49152                      // one 64-K half: [type][nt][hl][lane][16B]
#define BIG_BYTES  (2 * HALF_BYTES)           // 98304
#define SMEM_TOTAL (2 * BIG_BYTES)            // 196608

// B scratch, fragment-major fp16:
// [type(3)][ntile(32)][kchunk(128)][half(2)][lane(32)][16B] = 12.58 MB
__device__ __align__(256) uint8_t g_B[3u * 32u * 128u * 2u * 32u * 16u];

// per-(CTA, segment) fp32 partial tiles: 148 * 2 * 128*128 * 4B = 19.4 MB
__device__ __align__(256) float g_part[NCTA2][2][128 * 128];

#define BS_HALF   512u
#define BS_CHUNK  1024u
#define BS_NTILE  131072u
#define BS_TYPE   4194304u

#define S1_WFRAG_BYTES (16 * 8 * 32 * 8)      // 32768 (tbuf aliased inside)
#define S1_TBUF_BYTES  (32 * 66 * 2)          // 4224 per warp
#define S1_SMEM S1_WFRAG_BYTES

// ---------------- helpers ---------------------------------------------------

__device__ __forceinline__ uint32_t smem_u32(const void* p) {
    uint32_t a;
    asm("{ .reg .u64 t; cvta.to.shared.u64 t, %1; cvt.u32.u64 %0, t; }" : "=r"(a) : "l"(p));
    return a;
}

__device__ __forceinline__ uint32_t prmt(uint32_t a, uint32_t b, uint32_t sel) {
    uint32_t r;
    asm("prmt.b32 %0, %1, %2, %3;" : "=r"(r) : "r"(a), "r"(b), "r"(sel));
    return r;
}

__device__ __forceinline__ uint32_t pack4(int a, int b, int c, int d) {
    uint32_t x, y, r;
    asm("prmt.b32 %0, %1, %2, 0x40;"   : "=r"(x) : "r"(a), "r"(b));
    asm("prmt.b32 %0, %1, %2, 0x40;"   : "=r"(y) : "r"(c), "r"(d));
    asm("prmt.b32 %0, %1, %2, 0x5410;" : "=r"(r) : "r"(x), "r"(y));
    return r;
}

__device__ __forceinline__ uint32_t f2h2(float a, float b) {
    __half2 h = __floats2half2_rn(a, b);
    return *reinterpret_cast<uint32_t*>(&h);
}

__device__ __forceinline__ void mma_f16(float* c,
                                        uint32_t a0, uint32_t a1, uint32_t a2, uint32_t a3,
                                        uint32_t b0, uint32_t b1) {
    asm volatile(
        "mma.sync.aligned.m16n8k16.row.col.f32.f16.f16.f32 "
        "{%0,%1,%2,%3}, {%4,%5,%6,%7}, {%8,%9}, {%0,%1,%2,%3};"
        : "+f"(c[0]), "+f"(c[1]), "+f"(c[2]), "+f"(c[3])
        : "r"(a0), "r"(a1), "r"(a2), "r"(a3), "r"(b0), "r"(b1));
}

__device__ __forceinline__ void cp_async16(uint32_t smem_addr, const void* gptr) {
    asm volatile("cp.async.cg.shared.global [%0], [%1], 16;"
                 :: "r"(smem_addr), "l"(gptr) : "memory");
}
#define CP_COMMIT() asm volatile("cp.async.commit_group;" ::: "memory")
#define CP_WAIT0()  asm volatile("cp.async.wait_group 0;" ::: "memory")

// ---------------- Stage 1: H_k = V @ w_k on HMMA ----------------------------
// grid (64 j-tiles of 128, 4 n-quarters, 3 types), block 128 (4 warps).
// tbuf aliased over wfrag (wfrag dead after mainloop).

__global__ void __launch_bounds__(128)
stage1_kernel(const float* __restrict__ V,
              const float* __restrict__ w1,
              const float* __restrict__ w2,
              const float* __restrict__ w3) {
    extern __shared__ uint8_t s1mem[];
    const int j0 = blockIdx.x * 128;
    const int n0 = blockIdx.y * 64;
    const int type = blockIdx.z;
    const float* w = (type == 0) ? w1 : (type == 1) ? w2 : w3;

    const int tid = threadIdx.x;
    const int wid = tid >> 5, l = tid & 31;
    const int li = l & 3, lr = l >> 2;

    uint2* wfrag = (uint2*)s1mem;
#pragma unroll
    for (int q = 0; q < 32; q++) {
        int idx = tid + 128 * q;
        int ks = idx >> 8;
        int nt = (idx >> 5) & 7;
        int l2 = idx & 31;
        int n = n0 + 8 * nt + (l2 >> 2);
        int k0 = 16 * ks + 2 * (l2 & 3);
        float f0 = __ldg(&w[(size_t)k0 * 256 + n]);
        float f1 = __ldg(&w[(size_t)(k0 + 1) * 256 + n]);
        float f2 = __ldg(&w[(size_t)(k0 + 8) * 256 + n]);
        float f3 = __ldg(&w[(size_t)(k0 + 9) * 256 + n]);
        wfrag[idx] = make_uint2(f2h2(f0, f1), f2h2(f2, f3));
    }
    __syncthreads();

    const int rw = j0 + 32 * wid;
    float acc[2][8][4];
#pragma unroll
    for (int m = 0; m < 2; m++)
#pragma unroll
        for (int nt = 0; nt < 8; nt++)
#pragma unroll
            for (int r = 0; r < 4; r++) acc[m][nt][r] = 0.f;

#pragma unroll
    for (int ks = 0; ks < 16; ks++) {
        const int k0 = 16 * ks + 2 * li;
        uint32_t a[2][4];
#pragma unroll
        for (int m = 0; m < 2; m++) {
            const float* p0 = V + (size_t)(rw + 16 * m + lr) * 256;
            const float* p1 = p0 + 8 * 256;
            float2 x0 = *(const float2*)(p0 + k0);
            float2 x1 = *(const float2*)(p1 + k0);
            float2 x2 = *(const float2*)(p0 + k0 + 8);
            float2 x3 = *(const float2*)(p1 + k0 + 8);
            a[m][0] = f2h2(x0.x, x0.y);
            a[m][1] = f2h2(x1.x, x1.y);
            a[m][2] = f2h2(x2.x, x2.y);
            a[m][3] = f2h2(x3.x, x3.y);
        }
#pragma unroll
        for (int nt = 0; nt < 8; nt++) {
            uint2 bw = wfrag[(ks * 8 + nt) * 32 + l];
            mma_f16(acc[0][nt], a[0][0], a[0][1], a[0][2], a[0][3], bw.x, bw.y);
            mma_f16(acc[1][nt], a[1][0], a[1][1], a[1][2], a[1][3], bw.x, bw.y);
        }
    }

    __syncthreads();   // wfrag dead; alias tbuf over it
    __half* tb = (__half*)(s1mem + wid * S1_TBUF_BYTES);
#pragma unroll
    for (int m = 0; m < 2; m++) {
#pragma unroll
        for (int nt = 0; nt < 8; nt++) {
            const int jrow = 16 * m + lr;
            const int nloc = 8 * nt + 2 * li;
            __half2 lo = __floats2half2_rn(acc[m][nt][0], acc[m][nt][1]);
            __half2 hi = __floats2half2_rn(acc[m][nt][2], acc[m][nt][3]);
            *(__half2*)&tb[jrow * 66 + nloc] = lo;
            *(__half2*)&tb[(jrow + 8) * 66 + nloc] = hi;
        }
    }
    __syncwarp();

    const int kc = (j0 + 32 * wid) >> 6;
    const int hl = wid & 1;
#pragma unroll
    for (int nt = 0; nt < 8; nt++) {
        const int nloc = 8 * nt + lr;
        const int jb = 2 * li;
        ushort h[8];
#pragma unroll
        for (int i = 0; i < 2; i++) {
            h[4 * i + 0] = *(ushort*)&tb[(jb + 16 * i + 0) * 66 + nloc];
            h[4 * i + 1] = *(ushort*)&tb[(jb + 16 * i + 1) * 66 + nloc];
            h[4 * i + 2] = *(ushort*)&tb[(jb + 16 * i + 8) * 66 + nloc];
            h[4 * i + 3] = *(ushort*)&tb[(jb + 16 * i + 9) * 66 + nloc];
        }
        uint4 val;
        val.x = (uint32_t)h[0] | ((uint32_t)h[1] << 16);
        val.y = (uint32_t)h[2] | ((uint32_t)h[3] << 16);
        val.z = (uint32_t)h[4] | ((uint32_t)h[5] << 16);
        val.w = (uint32_t)h[6] | ((uint32_t)h[7] << 16);
        size_t off = (size_t)type * BS_TYPE
                   + (size_t)(blockIdx.y * 8 + nt) * BS_NTILE
                   + (size_t)kc * BS_CHUNK + (size_t)hl * BS_HALF + (size_t)l * 16;
        *(uint4*)&g_B[off] = val;
    }
}

// ---------------- Stage 2: mask-GEMM, balanced, K128 chunks, 1 barrier ------
// grid 148, 256 threads. CTA i owns units [8192i/148, 8192(i+1)/148) where a
// unit = (tile, bigchunk of K=128). 1-2 segments per CTA. Partials to g_part.

__global__ void __launch_bounds__(256, 1)
stage2_kernel(const int* __restrict__ adj) {
    extern __shared__ uint8_t smem[];
    const uint32_t smem_base = smem_u32(smem);

    const int tid = threadIdx.x;
    const int wid = tid >> 5, l = tid & 31;
    const int li = l & 3;

    const uint32_t ci = blockIdx.x;
    const uint32_t start = (uint32_t)(((uint64_t)TOTUNITS * ci) / NCTA2);
    const uint32_t end   = (uint32_t)(((uint64_t)TOTUNITS * (ci + 1)) / NCTA2);
    const int t0 = (int)(start >> 6), t1 = (int)((end - 1) >> 6);
    const int nseg = (t1 > t0) ? 2 : 1;

    for (int sgi = 0; sgi < nseg; sgi++) {
        const int tile = (sgi == 0) ? t0 : t1;
        const int clo = (sgi == 0) ? (int)(start & 63u) : 0;
        const int chi = (sgi == 0) ? ((t1 > t0) ? NBIG : (int)(end - ((uint32_t)t0 << 6)))
                                   : (int)(end - ((uint32_t)t1 << 6));
        const int m_tile = tile >> 1;
        const int n_half = tile & 1;
        const int i0 = m_tile * 128;

        const int rowA = i0 + wid * 16 + (l >> 2);
        const int2* aA = (const int2*)(adj + (size_t)rowA * NROWS);
        const int2* aB = (const int2*)(adj + (size_t)(rowA + 8) * NROWS);

        float acc[16][4];
#pragma unroll
        for (int nt = 0; nt < 16; nt++)
#pragma unroll
            for (int r = 0; r < 4; r++) acc[nt][r] = 0.f;

        // prologue: stage bigchunk clo (2 x 64K halves = 24 cp.async / thread)
        {
            const int p = clo;
#pragma unroll
            for (int hc = 0; hc < 2; hc++) {
#pragma unroll
                for (int q = 0; q < 12; q++) {
                    int idx = tid + 256 * q;
                    int type = idx >> 10;
                    int rem = idx & 1023;
                    int nt = rem >> 6;
                    int hl = (rem >> 5) & 1;
                    int lane = rem & 31;
                    const uint8_t* src = g_B + (size_t)type * BS_TYPE
                        + (size_t)(n_half * 16 + nt) * BS_NTILE
                        + (size_t)(2 * p + hc) * BS_CHUNK
                        + (size_t)hl * BS_HALF + (size_t)lane * 16;
                    cp_async16(smem_base + (p & 1) * BIG_BYTES + hc * HALF_BYTES + idx * 16,
                               src);
                }
            }
            CP_COMMIT();
        }

        // preload adj for first 64-K half of clo
        int2 vA0[4], vA1[4], vB0[4], vB1[4];
        {
            const int base = (2 * clo) * 32;
#pragma unroll
            for (int s = 0; s < 4; s++) {
                vA0[s] = aA[base + 8 * s + li];
                vA1[s] = aA[base + 8 * s + li + 4];
                vB0[s] = aB[base + 8 * s + li];
                vB1[s] = aB[base + 8 * s + li + 4];
            }
        }

        for (int c = clo; c < chi; c++) {
            CP_WAIT0();        // bigchunk c fully landed (this thread's groups)
            __syncthreads();   // visibility + buffer (c-1)&1 free for overwrite

            // stage bigchunk c+1 (streams in under this chunk's MMAs)
            if (c + 1 < chi) {
                const int p = c + 1;
#pragma unroll
                for (int hc = 0; hc < 2; hc++) {
#pragma unroll
                    for (int q = 0; q < 12; q++) {
                        int idx = tid + 256 * q;
                        int type = idx >> 10;
                        int rem = idx & 1023;
                        int nt = rem >> 6;
                        int hl = (rem >> 5) & 1;
                        int lane = rem & 31;
                        const uint8_t* src = g_B + (size_t)type * BS_TYPE
                            + (size_t)(n_half * 16 + nt) * BS_NTILE
                            + (size_t)(2 * p + hc) * BS_CHUNK
                            + (size_t)hl * BS_HALF + (size_t)lane * 16;
                        cp_async16(smem_base + (p & 1) * BIG_BYTES + hc * HALF_BYTES + idx * 16,
                                   src);
                    }
                }
            }
            CP_COMMIT();

            // two 64-K halves
#pragma unroll
            for (int hc = 0; hc < 2; hc++) {
                // pack adj for this half
                uint32_t pkA[4], pkB[4];
#pragma unroll
                for (int s = 0; s < 4; s++) {
                    pkA[s] = pack4(vA0[s].x, vA0[s].y, vA1[s].x, vA1[s].y);
                    pkB[s] = pack4(vB0[s].x, vB0[s].y, vB1[s].x, vB1[s].y);
                }
                // prefetch adj for next half (WAR-safe: pk already extracted)
                {
                    const int co2 = 2 * c + hc + 1;
                    if (co2 < 2 * chi) {
                        const int base = co2 * 32;
#pragma unroll
                        for (int s = 0; s < 4; s++) {
                            vA0[s] = aA[base + 8 * s + li];
                            vA1[s] = aA[base + 8 * s + li + 4];
                            vB0[s] = aB[base + 8 * s + li];
                            vB1[s] = aB[base + 8 * s + li + 4];
                        }
                    }
                }

                const uint32_t sb = smem_base + (c & 1) * BIG_BYTES + hc * HALF_BYTES;
#pragma unroll
                for (int t = 0; t < 3; t++) {
                    const uint32_t cmp = 0x01010101u * (t + 1);
                    uint32_t am[4][4];
#pragma unroll
                    for (int s = 0; s < 4; s++) {
                        uint32_t eA = __vcmpeq4(pkA[s], cmp) & 0x3C3C3C3Cu;
                        uint32_t eB = __vcmpeq4(pkB[s], cmp) & 0x3C3C3C3Cu;
                        am[s][0] = prmt(eA, 0u, 0x1404u);
                        am[s][1] = prmt(eB, 0u, 0x1404u);
                        am[s][2] = prmt(eA, 0u, 0x3424u);
                        am[s][3] = prmt(eB, 0u, 0x3424u);
                    }
#pragma unroll
                    for (int nt = 0; nt < 16; nt++) {
                        const uint32_t base = sb + (uint32_t)(((t * 16 + nt) * 2) * 512 + l * 16);
                        uint4 u0, u1;
                        asm volatile("ld.shared.v4.u32 {%0,%1,%2,%3}, [%4];"
                                     : "=r"(u0.x), "=r"(u0.y), "=r"(u0.z), "=r"(u0.w) : "r"(base));
                        asm volatile("ld.shared.v4.u32 {%0,%1,%2,%3}, [%4];"
                                     : "=r"(u1.x), "=r"(u1.y), "=r"(u1.z), "=r"(u1.w) : "r"(base + 512));
                        mma_f16(acc[nt], am[0][0], am[0][1], am[0][2], am[0][3], u0.x, u0.y);
                        mma_f16(acc[nt], am[1][0], am[1][1], am[1][2], am[1][3], u0.z, u0.w);
                        mma_f16(acc[nt], am[2][0], am[2][1], am[2][2], am[2][3], u1.x, u1.y);
                        mma_f16(acc[nt], am[3][0], am[3][1], am[3][2], am[3][3], u1.z, u1.w);
                    }
                }
            }
        }

        // segment epilogue: partials (no bias)
        float* part = g_part[ci][sgi];
        const int rloc = wid * 16 + (l >> 2);
#pragma unroll
        for (int nt = 0; nt < 16; nt++) {
            int col = nt * 8 + 2 * li;
            *(float2*)&part[rloc * 128 + col] = make_float2(acc[nt][0], acc[nt][1]);
            *(float2*)&part[(rloc + 8) * 128 + col] = make_float2(acc[nt][2], acc[nt][3]);
        }
        __syncthreads();   // protect smem before next segment's prologue
    }
}

// ---------------- Fixup: sum partials per tile + bias -----------------------
// grid 128 (one CTA per tile), 256 threads.

__global__ void __launch_bounds__(256)
fixup_kernel(const float* __restrict__ bias, float* __restrict__ out) {
    const int t = blockIdx.x;
    const int m_tile = t >> 1, n_half = t & 1;
    const int i0 = m_tile * 128;
    const int n0 = n_half * 128;

    int src_i[3], src_s[3];
    int ns = 0;
    int ic = (t * NCTA2) >> 7;
    int lo = ic - 1 < 0 ? 0 : ic - 1;
    int hi = ic + 2 > NCTA2 - 1 ? NCTA2 - 1 : ic + 2;
    for (int i = lo; i <= hi; i++) {
        uint32_t s0 = (uint32_t)(((uint64_t)TOTUNITS * i) / NCTA2);
        uint32_t e0 = (uint32_t)(((uint64_t)TOTUNITS * (i + 1)) / NCTA2);
        int tt0 = (int)(s0 >> 6), tt1 = (int)((e0 - 1) >> 6);
        if (tt0 == t)                      { src_i[ns] = i; src_s[ns] = 0; ns++; }
        else if (tt1 == t && tt1 != tt0)   { src_i[ns] = i; src_s[ns] = 1; ns++; }
    }

    for (int e = threadIdx.x; e < 4096; e += 256) {
        const int r = e >> 5;
        const int c4 = (e & 31) * 4;
        float4 s = make_float4(0.f, 0.f, 0.f, 0.f);
        for (int k = 0; k < ns; k++) {
            float4 v = *(const float4*)&g_part[src_i[k]][src_s[k]][r * 128 + c4];
            s.x += v.x; s.y += v.y; s.z += v.z; s.w += v.w;
        }
        float4 b = *(const float4*)&bias[n0 + c4];
        s.x += b.x; s.y += b.y; s.z += b.z; s.w += b.w;
        *(float4*)&out[(size_t)(i0 + r) * FEAT + n0 + c4] = s;
    }
}

// ---------------- launch ---------------------------------------------------

extern "C" void kernel_launch(void* const* d_in, const int* in_sizes, int n_in,
                              void* d_out, int out_size) {
    const float* V    = (const float*)d_in[0];
    const int*   adj  = (const int*)d_in[1];
    const float* w1   = (const float*)d_in[2];
    const float* w2   = (const float*)d_in[3];
    const float* w3   = (const float*)d_in[4];
    const float* bias = (const float*)d_in[5];
    float* out = (float*)d_out;

    cudaFuncSetAttribute(stage1_kernel,
                         cudaFuncAttributeMaxDynamicSharedMemorySize, S1_SMEM);
    cudaFuncSetAttribute(stage2_kernel,
                         cudaFuncAttributeMaxDynamicSharedMemorySize, SMEM_TOTAL);

    stage1_kernel<<<dim3(64, 4, 3), 128, S1_SMEM>>>(V, w1, w2, w3);
    stage2_kernel<<<NCTA2, 256, SMEM_TOTAL>>>(adj);
    fixup_kernel<<<128, 256>>>(bias, out);
}